// round 13
// baseline (speedup 1.0000x reference)
#include <cuda_runtime.h>
#include <cuda_bf16.h>

typedef unsigned int u32;

// ---------------------------------------------------------------------------
// Problem constants
// ---------------------------------------------------------------------------
namespace {
constexpr int kT = 2048;
constexpr int kS = 512;
constexpr int kB = 16;
constexpr int kA = 18;
constexpr int kColsTot = 336;           // 288 + 32 + 16
constexpr int kRowsPerBlk = 16;
constexpr int kBlkSteps = 16;
constexpr int kNBlks = 128;
constexpr int kGrid1 = 129;
constexpr int kThreads = 672;           // 21 warps
constexpr int kK2 = 256;                // k-pairs (bf16x2 along K)
constexpr int kAStrideU = 260;          // smA row stride (u32)
constexpr int kWStrideU = 36;           // smW col stride (u32)
constexpr int kTileK2 = 32;             // k-pairs per W tile
constexpr int kNIt = 8;
constexpr int kWTileU = kColsTot * kWStrideU;   // 12096
// K1 smem layout (u32 units)
constexpr int kOffA  = 0;                        // 16*260 = 4160
constexpr int kOffW  = 4160;                     // 3 tiles -> 40448
constexpr int kOffE0 = 40448;
constexpr int kOffE1 = kOffE0 + 256;
constexpr int kOffEs = kOffE1 + 256;
constexpr int kOffEa = kOffEs + 256;
constexpr int kSmem1U = kOffEa + 256;            // 41472
constexpr int kSmem1B = kSmem1U * 4;             // 165888
// K2 smem layout (float units)
constexpr int kMStrideRow = 20;
constexpr int kMStrideMat = 320;
constexpr int kOffChk = 128 * kMStrideMat;       // 40960 (2064 floats)
constexpr int kOffEx  = kOffChk + 2064;          // 43024 (129 ints)
constexpr int kOffRed = 43156;                   // byte 172624, 8-aligned
constexpr int kSmem2F = kOffRed + 48;            // 21 doubles fits
constexpr int kSmem2B = kSmem2F * 4;             // 172816
}
#define EXP_NEG_PEN 0.60653065971263342f
#define LN2 0.69314718055994530942

// Cross-kernel scratch.
__device__ u32    g_WbT[kColsTot * kK2];   // W transposed, bf16x2 k-paired
__device__ float  g_M[kNBlks * 256];       // composed block matrices
__device__ float  g_Y[kT * kB];            // y_s = P_s^T eac_s per step
__device__ float  g_q0[kB];                // start softmax row 0
__device__ float  g_es0_fin[kB];           // stop0 softmax row 2048

// ---------------------------------------------------------------------------
// helpers
// ---------------------------------------------------------------------------
__device__ __forceinline__ void cp_async16(void* sdst, const void* gsrc) {
    unsigned a = (unsigned)__cvta_generic_to_shared(sdst);
    asm volatile("cp.async.cg.shared.global [%0], [%1], 16;" :: "r"(a), "l"(gsrc));
}
#define CP_COMMIT() asm volatile("cp.async.commit_group;")
#define CP_WAIT1()  asm volatile("cp.async.wait_group 1;")
#define CP_WAIT0()  asm volatile("cp.async.wait_group 0;")

__device__ __forceinline__ u32 pack_bf16(float lo, float hi) {
    unsigned short l = __bfloat16_as_ushort(__float2bfloat16_rn(lo));
    unsigned short h = __bfloat16_as_ushort(__float2bfloat16_rn(hi));
    return ((u32)h << 16) | (u32)l;
}
__device__ __forceinline__ void mma_bf16(float c[4], u32 a0, u32 a1, u32 a2,
                                         u32 a3, u32 b0, u32 b1) {
    asm("mma.sync.aligned.m16n8k16.row.col.f32.bf16.bf16.f32 "
        "{%0,%1,%2,%3},{%4,%5,%6,%7},{%8,%9},{%0,%1,%2,%3};"
        : "+f"(c[0]), "+f"(c[1]), "+f"(c[2]), "+f"(c[3])
        : "r"(a0), "r"(a1), "r"(a2), "r"(a3), "r"(b0), "r"(b1));
}
__device__ __forceinline__ void load16s(float d[16], const float* p) {
    const float4* p4 = (const float4*)p;
    float4 a = p4[0], b = p4[1], c = p4[2], e = p4[3];
    d[0]=a.x; d[1]=a.y; d[2]=a.z; d[3]=a.w;
    d[4]=b.x; d[5]=b.y; d[6]=b.z; d[7]=b.w;
    d[8]=c.x; d[9]=c.y; d[10]=c.z; d[11]=c.w;
    d[12]=e.x; d[13]=e.y; d[14]=e.z; d[15]=e.w;
}
__device__ __forceinline__ float tree16(const float v[16]) {
    float a0=v[0]+v[1], a1=v[2]+v[3], a2=v[4]+v[5], a3=v[6]+v[7];
    float a4=v[8]+v[9], a5=v[10]+v[11], a6=v[12]+v[13], a7=v[14]+v[15];
    float b0=a0+a1, b1=a2+a3, b2=a4+a5, b3=a6+a7;
    return (b0+b1)+(b2+b3);
}

// ---------------------------------------------------------------------------
// K0: convert W -> transposed bf16 pairs
// ---------------------------------------------------------------------------
__global__ __launch_bounds__(256) void convert_w_kernel(
    const float* __restrict__ Wa,
    const float* __restrict__ Wsp,
    const float* __restrict__ Wst) {
    int idx = blockIdx.x * 256 + threadIdx.x;
    if (idx >= kColsTot * kK2) return;
    int k2 = idx / kColsTot;
    int col = idx - k2 * kColsTot;
    const float* base; int stride, off;
    if (col < 288)      { base = Wa;  stride = 288; off = col; }
    else if (col < 320) { base = Wsp; stride = 32;  off = col - 288; }
    else                { base = Wst; stride = 16;  off = col - 320; }
    float x0 = base[(2 * k2    ) * stride + off];
    float x1 = base[(2 * k2 + 1) * stride + off];
    g_WbT[col * kK2 + k2] = pack_bf16(x0, x1);
}

// ---------------------------------------------------------------------------
// K1: A-pack + bf16 TC GEMM + softmax + compose (+ y-vectors)
// ---------------------------------------------------------------------------
__global__ __launch_bounds__(kThreads) void gemm_kernel(
    const float* __restrict__ s_i,
    const void* __restrict__ actions_raw) {
    extern __shared__ __align__(16) u32 smem[];
    u32* smA = smem + kOffA;
    u32* smW = smem + kOffW;
    float* smL = (float*)(smem + kOffW);
    float* sE0 = (float*)(smem + kOffE0);
    float* sE1 = (float*)(smem + kOffE1);
    float* sEs = (float*)(smem + kOffEs);
    float* sEa = (float*)(smem + kOffEa);
    __shared__ int s_is64;

    const int tid  = threadIdx.x;
    const int blk  = blockIdx.x;
    const int row0 = blk * kRowsPerBlk;

    if (tid == 0) {
        const unsigned* w = (const unsigned*)actions_raw;
        unsigned acc = 0;
#pragma unroll
        for (int j = 1; j < 64; j += 2) acc |= w[j];
        s_is64 = (acc == 0u) ? 1 : 0;
    }

    // W prestage: tiles p0, p0+1
    const int p0 = blk & (kNIt - 1);
    {
        int tk2 = p0 * kTileK2;
#pragma unroll
        for (int h = 0; h < 4; h++) {
            int q = tid + h * kThreads;
            int col = q >> 3, ch = q & 7;
            cp_async16(smW + col * kWStrideU + ch * 4,
                       g_WbT + col * kK2 + tk2 + ch * 4);
        }
        CP_COMMIT();
        int tk2b = (((p0 + 1) & (kNIt - 1)) * kTileK2);
#pragma unroll
        for (int h = 0; h < 4; h++) {
            int q = tid + h * kThreads;
            int col = q >> 3, ch = q & 7;
            cp_async16(smW + kWTileU + col * kWStrideU + ch * 4,
                       g_WbT + col * kK2 + tk2b + ch * 4);
        }
        CP_COMMIT();
    }

    // A-pack: fp32 -> bf16 pairs in registers -> smem
#pragma unroll
    for (int h = 0; h < 2; h++) {
        int q = tid + h * kThreads;
        if (q < 1024) {
            int r  = q >> 6;
            int ch = q & 63;
            int gr = row0 + r;
            float4 f0 = make_float4(0.f, 0.f, 0.f, 0.f);
            float4 f1 = f0;
            if (gr <= kT) {
                const float4* src = (const float4*)(s_i + gr * kS + ch * 8);
                f0 = src[0];
                f1 = src[1];
            }
            uint4 pk;
            pk.x = pack_bf16(f0.x, f0.y);
            pk.y = pack_bf16(f0.z, f0.w);
            pk.z = pack_bf16(f1.x, f1.y);
            pk.w = pack_bf16(f1.z, f1.w);
            *(uint4*)(smA + r * kAStrideU + ch * 4) = pk;
        }
    }

    // GEMM (bf16 m16n8k16)
    const int lane = tid & 31;
    const int wid  = tid >> 5;
    const int g    = lane >> 2;
    const int t    = lane & 3;
    const int cb0  = wid * 16;
    const int cb1  = cb0 + 8;

    float c0[4] = {0.f, 0.f, 0.f, 0.f};
    float c1[4] = {0.f, 0.f, 0.f, 0.f};

    for (int i = 0; i < kNIt; i++) {
        if (i == kNIt - 1) { CP_WAIT0(); } else { CP_WAIT1(); }
        __syncthreads();
        if (i + 2 < kNIt) {
            u32* d = smW + ((i + 2) % 3) * kWTileU;
            int tk2 = (((p0 + i + 2) & (kNIt - 1)) * kTileK2);
#pragma unroll
            for (int h = 0; h < 4; h++) {
                int q = tid + h * kThreads;
                int col = q >> 3, ch = q & 7;
                cp_async16(d + col * kWStrideU + ch * 4,
                           g_WbT + col * kK2 + tk2 + ch * 4);
            }
            CP_COMMIT();
        }
        const int phys = (p0 + i) & (kNIt - 1);
        const u32* wt = smW + (i % 3) * kWTileU;
        const int kb2 = phys * kTileK2;
#pragma unroll
        for (int kk = 0; kk < 4; kk++) {
            const int o  = kb2 + kk * 8;
            const int ot = kk * 8;
            u32 a0 = smA[(g    ) * kAStrideU + o + t    ];
            u32 a1 = smA[(g + 8) * kAStrideU + o + t    ];
            u32 a2 = smA[(g    ) * kAStrideU + o + t + 4];
            u32 a3 = smA[(g + 8) * kAStrideU + o + t + 4];
            u32 b00 = wt[(cb0 + g) * kWStrideU + ot + t    ];
            u32 b01 = wt[(cb0 + g) * kWStrideU + ot + t + 4];
            u32 b10 = wt[(cb1 + g) * kWStrideU + ot + t    ];
            u32 b11 = wt[(cb1 + g) * kWStrideU + ot + t + 4];
            mma_bf16(c0, a0, a1, a2, a3, b00, b01);
            mma_bf16(c1, a0, a1, a2, a3, b10, b11);
        }
    }
    __syncthreads();

    // epilogue: scatter fragments to smL[r*336 + c]
    {
        int col0 = cb0 + 2 * t;
        smL[(g    ) * kColsTot + col0    ] = c0[0];
        smL[(g    ) * kColsTot + col0 + 1] = c0[1];
        smL[(g + 8) * kColsTot + col0    ] = c0[2];
        smL[(g + 8) * kColsTot + col0 + 1] = c0[3];
        int col1 = cb1 + 2 * t;
        smL[(g    ) * kColsTot + col1    ] = c1[0];
        smL[(g    ) * kColsTot + col1 + 1] = c1[1];
        smL[(g + 8) * kColsTot + col1    ] = c1[2];
        smL[(g + 8) * kColsTot + col1 + 1] = c1[3];
    }
    __syncthreads();

    // softmaxes (smem only; tiny global stores for rows 0 / 2048)
    if (tid < 256) {
        const int r = tid >> 4;
        const int b = tid & 15;
        const int i = row0 + r;
        const bool valid = (i <= kT);
        const int is64 = s_is64;

        if (valid) {
            if (i < kT) {
                int a;
                if (is64) a = (int)((const long long*)actions_raw)[i];
                else      a = ((const int*)actions_raw)[i];
                const float* L = &smL[r * kColsTot + b * kA];
                float m = L[0];
#pragma unroll
                for (int j = 1; j < kA; j++) m = fmaxf(m, L[j]);
                float s = 0.0f;
#pragma unroll
                for (int j = 0; j < kA; j++) s += __expf(L[j] - m);
                sEa[r * kB + b] = __expf(L[a] - m) / s;
            }
            float x0 = smL[r * kColsTot + 288 + 2 * b];
            float x1 = smL[r * kColsTot + 288 + 2 * b + 1];
            float m = fmaxf(x0, x1);
            float e0 = __expf(x0 - m), e1 = __expf(x1 - m);
            float inv = 1.0f / (e0 + e1);
            float es0 = e0 * inv;
            sE0[r * kB + b] = es0;
            sE1[r * kB + b] = e1 * inv;
            if (i == kT) g_es0_fin[b] = es0;
        }
        {
            float x = smL[r * kColsTot + 320 + b];
            float m = x;
            m = fmaxf(m, __shfl_xor_sync(0xFFFFFFFFu, m, 1));
            m = fmaxf(m, __shfl_xor_sync(0xFFFFFFFFu, m, 2));
            m = fmaxf(m, __shfl_xor_sync(0xFFFFFFFFu, m, 4));
            m = fmaxf(m, __shfl_xor_sync(0xFFFFFFFFu, m, 8));
            float e = __expf(x - m);
            float s = e;
            s += __shfl_xor_sync(0xFFFFFFFFu, s, 1);
            s += __shfl_xor_sync(0xFFFFFFFFu, s, 2);
            s += __shfl_xor_sync(0xFFFFFFFFu, s, 4);
            s += __shfl_xor_sync(0xFFFFFFFFu, s, 8);
            if (valid) {
                float es = e / s;
                sEs[r * kB + b] = es;
                if (i == 0) g_q0[b] = es;
            }
        }
    }
    __syncthreads();

    // compose 16 step-maps -> g_M[blk], emitting y_s = P_s^T eac_s per step
    if (blk < kNBlks && tid < 32) {
        const int k = tid & 15;
        float P16[16];
#pragma unroll
        for (int j = 0; j < 16; j++) P16[j] = (j == k) ? 1.0f : 0.0f;
        for (int s = 0; s < kBlkSteps; s++) {
            if (!(blk == 0 && s == 0)) {
                float s0[16], s1[16], vv[16];
                load16s(s0, &sE0[s * kB]);
                load16s(s1, &sE1[s * kB]);
                load16s(vv, &sEs[s * kB]);
                float m[16];
#pragma unroll
                for (int j = 0; j < 16; j++) m[j] = s1[j] * P16[j];
                float w = tree16(m);
#pragma unroll
                for (int j = 0; j < 16; j++)
                    P16[j] = fmaf(s0[j], P16[j], (vv[j] * EXP_NEG_PEN) * w);
            }
            // y_s[k] = sum_j eac_s[j] * P[j,k]
            float ea[16];
            load16s(ea, &sEa[s * kB]);
            float m2[16];
#pragma unroll
            for (int j = 0; j < 16; j++) m2[j] = ea[j] * P16[j];
            float y = tree16(m2);
            if (tid < 16)
                g_Y[(blk * kBlkSteps + s) * kB + k] = y;
        }
        if (tid < 16) {
#pragma unroll
            for (int j = 0; j < 16; j++)
                g_M[blk * 256 + j * 16 + k] = P16[j];
        }
    }
}

// ---------------------------------------------------------------------------
// K2: serial scan over 128 block matrices + fully parallel tot reduction
// ---------------------------------------------------------------------------
__global__ __launch_bounds__(kThreads) void scan_kernel(float* __restrict__ out) {
    extern __shared__ __align__(16) u32 smemu[];
    float* smM   = (float*)smemu;
    float* sChk  = (float*)smemu + kOffChk;    // 129 x 16
    int*   sEx   = (int*)((float*)smemu + kOffEx);
    double* sRed = (double*)((float*)smemu + kOffRed);
    const int tid = threadIdx.x;

    // preload all 128 matrices into padded smem
#pragma unroll
    for (int h = 0; h < 13; h++) {
        int q = tid + h * kThreads;
        if (q < 8192) {
            int m   = q >> 6;
            int rem = q & 63;
            int row = rem >> 2;
            int ch  = rem & 3;
            cp_async16(smM + m * kMStrideMat + row * kMStrideRow + ch * 4,
                       (const float*)g_M + q * 4);
        }
    }
    CP_COMMIT();
    CP_WAIT0();
    __syncthreads();

    // serial scan: warp 0
    if (tid < 32) {
        const int r = tid & 15;
        float Q[16];
        load16s(Q, g_q0);
        if (tid < 16) sChk[tid] = Q[tid];
        if (tid == 0) sEx[0] = 0;
        int E = 0;

        const float* Mr = smM + r * kMStrideRow;
        float4 a0 = *(const float4*)(Mr + 0);
        float4 a1 = *(const float4*)(Mr + 4);
        float4 a2 = *(const float4*)(Mr + 8);
        float4 a3 = *(const float4*)(Mr + 12);

        for (int j = 0; j < kNBlks; j++) {
            float4 b0, b1, b2, b3;
            if (j + 1 < kNBlks) {
                const float* Mn = smM + (j + 1) * kMStrideMat + r * kMStrideRow;
                b0 = *(const float4*)(Mn + 0);
                b1 = *(const float4*)(Mn + 4);
                b2 = *(const float4*)(Mn + 8);
                b3 = *(const float4*)(Mn + 12);
            }
            float mm[16] = {a0.x, a0.y, a0.z, a0.w, a1.x, a1.y, a1.z, a1.w,
                            a2.x, a2.y, a2.z, a2.w, a3.x, a3.y, a3.z, a3.w};
            float pr[16];
#pragma unroll
            for (int kk = 0; kk < 16; kk++) pr[kk] = mm[kk] * Q[kk];
            float outr = tree16(pr);

            float Qn[16];
#pragma unroll
            for (int kk = 0; kk < 16; kk++)
                Qn[kk] = __shfl_sync(0xFFFFFFFFu, outr, kk);

            if ((j & 3) == 3) {
                float ss = tree16(Qn);
                int e = ((__float_as_int(ss) >> 23) & 0xFF) - 127;
                float sc = __int_as_float((127 - e) << 23);
#pragma unroll
                for (int kk = 0; kk < 16; kk++) Q[kk] = Qn[kk] * sc;
                E += e;
            } else {
#pragma unroll
                for (int kk = 0; kk < 16; kk++) Q[kk] = Qn[kk];
            }

            if (tid < 16) sChk[(j + 1) * kB + tid] = Q[tid];
            if (tid == 0) sEx[j + 1] = E;
            a0 = b0; a1 = b1; a2 = b2; a3 = b3;
        }
    }
    __syncthreads();

    // parallel tot: each thread handles steps tid, tid+672, ...
    double acc = 0.0;
    for (int st = tid; st < kT; st += kThreads) {
        const int bj = st >> 4;
        float y[16], c[16];
        load16s(y, &g_Y[st * kB]);
        load16s(c, &sChk[bj * kB]);
        float pr[16];
#pragma unroll
        for (int kk = 0; kk < 16; kk++) pr[kk] = y[kk] * c[kk];
        float u = tree16(pr);
        acc += (double)__logf(u) + (double)sEx[bj] * LN2;
    }
    if (tid == 0) {
        // final stop term: es0_fin . chk_128
        float f[16], c[16];
        load16s(f, g_es0_fin);
        load16s(c, &sChk[kNBlks * kB]);
        float pr[16];
#pragma unroll
        for (int kk = 0; kk < 16; kk++) pr[kk] = f[kk] * c[kk];
        float u = tree16(pr);
        acc += (double)__logf(u) + (double)sEx[kNBlks] * LN2;
    }

    // deterministic reduction: warp shfl then cross-warp via smem
#pragma unroll
    for (int o = 16; o > 0; o >>= 1)
        acc += __shfl_down_sync(0xFFFFFFFFu, acc, o);
    if ((tid & 31) == 0) sRed[tid >> 5] = acc;
    __syncthreads();
    if (tid == 0) {
        double tot = 0.0;
#pragma unroll
        for (int w = 0; w < kThreads / 32; w++) tot += sRed[w];
        out[0] = (float)tot;
    }
}

// ---------------------------------------------------------------------------
// Launch
// ---------------------------------------------------------------------------
extern "C" void kernel_launch(void* const* d_in, const int* in_sizes, int n_in,
                              void* d_out, int out_size) {
    const float* s_i = (const float*)d_in[0];
    const float* Wa  = (const float*)d_in[1];
    const float* Wsp = (const float*)d_in[2];
    const float* Wst = (const float*)d_in[3];
    const void*  act = d_in[4];

    cudaFuncSetAttribute(gemm_kernel,
                         cudaFuncAttributeMaxDynamicSharedMemorySize, kSmem1B);
    cudaFuncSetAttribute(scan_kernel,
                         cudaFuncAttributeMaxDynamicSharedMemorySize, kSmem2B);

    convert_w_kernel<<<(kColsTot * kK2 + 255) / 256, 256>>>(Wa, Wsp, Wst);
    gemm_kernel<<<kGrid1, kThreads, kSmem1B>>>(s_i, act);
    scan_kernel<<<1, kThreads, kSmem2B>>>((float*)d_out);
}

// round 14
// speedup vs baseline: 1.4199x; 1.4199x over previous
#include <cuda_runtime.h>
#include <cuda_bf16.h>

typedef unsigned int u32;

// ---------------------------------------------------------------------------
// Problem constants
// ---------------------------------------------------------------------------
namespace {
constexpr int kT = 2048;
constexpr int kS = 512;
constexpr int kB = 16;
constexpr int kA = 18;
constexpr int kColsTot = 336;           // 288 + 32 + 16
constexpr int kRowsPerBlk = 16;
constexpr int kBlkSteps = 16;
constexpr int kNBlks = 128;
constexpr int kGrid = 129;
constexpr int kThreads = 672;           // 21 warps
constexpr int kK2 = 256;                // k-pairs (bf16x2 along K)
constexpr int kAStrideU = 260;          // smA row stride (u32)
constexpr int kWStrideU = 36;           // smW col stride (u32)
constexpr int kTileK2 = 32;             // k-pairs per W tile
constexpr int kNIt = 8;
constexpr int kWTileU = kColsTot * kWStrideU;   // 12096
// smem layout (u32 units)
constexpr int kOffA  = 0;                        // 16*260 = 4160
constexpr int kOffW  = 4160;                     // 3 tiles -> 40448
// serial-phase M cache spans [0, 40960)
constexpr int kOffE0 = 41984;
constexpr int kOffE1 = kOffE0 + 256;
constexpr int kOffEs = kOffE1 + 256;
constexpr int kOffEa = kOffEs + 256;
constexpr int kOffY  = kOffEa + 256;             // 43008: y vectors 16x16
constexpr int kSmemU = kOffY + 256;              // 43264
constexpr int kSmemBytes = kSmemU * 4;           // 173056
constexpr int kMStrideRow = 20;
constexpr int kMStrideMat = 320;
}
#define EXP_NEG_PEN 0.60653065971263342f
#define LN2 0.69314718055994530942

// Cross-kernel / cross-block scratch.
__device__ u32    g_WbT[kColsTot * kK2];   // W transposed, bf16x2 k-paired
__device__ float  g_M[kNBlks * 256];
__device__ float  g_chk[(kNBlks + 1) * kB];
__device__ int    g_Eb[kNBlks + 1];
__device__ float  g_es0_fin[kB];
__device__ double g_tot;
__device__ unsigned g_mcnt;
__device__ unsigned g_rcnt;

struct Bar { unsigned cnt; unsigned gen; };
__device__ Bar g_bars[2];

__device__ __forceinline__ void gbar(int id, unsigned nb) {
    __syncthreads();
    if (threadIdx.x == 0) {
        __threadfence();
        volatile unsigned* vgen = &g_bars[id].gen;
        unsigned g0 = *vgen;
        unsigned prev = atomicAdd(&g_bars[id].cnt, 1u);
        if (prev == nb - 1u) {
            g_bars[id].cnt = 0u;
            __threadfence();
            atomicAdd(&g_bars[id].gen, 1u);
        } else {
            while (*vgen == g0) { __nanosleep(64); }
            __threadfence();
        }
    }
    __syncthreads();
}

// ---------------------------------------------------------------------------
// helpers
// ---------------------------------------------------------------------------
__device__ __forceinline__ void cp_async16(void* sdst, const void* gsrc) {
    unsigned a = (unsigned)__cvta_generic_to_shared(sdst);
    asm volatile("cp.async.cg.shared.global [%0], [%1], 16;" :: "r"(a), "l"(gsrc));
}
#define CP_COMMIT() asm volatile("cp.async.commit_group;")
#define CP_WAIT1()  asm volatile("cp.async.wait_group 1;")
#define CP_WAIT0()  asm volatile("cp.async.wait_group 0;")

__device__ __forceinline__ u32 pack_bf16(float lo, float hi) {
    unsigned short l = __bfloat16_as_ushort(__float2bfloat16_rn(lo));
    unsigned short h = __bfloat16_as_ushort(__float2bfloat16_rn(hi));
    return ((u32)h << 16) | (u32)l;
}
__device__ __forceinline__ void mma_bf16(float c[4], u32 a0, u32 a1, u32 a2,
                                         u32 a3, u32 b0, u32 b1) {
    asm("mma.sync.aligned.m16n8k16.row.col.f32.bf16.bf16.f32 "
        "{%0,%1,%2,%3},{%4,%5,%6,%7},{%8,%9},{%0,%1,%2,%3};"
        : "+f"(c[0]), "+f"(c[1]), "+f"(c[2]), "+f"(c[3])
        : "r"(a0), "r"(a1), "r"(a2), "r"(a3), "r"(b0), "r"(b1));
}
__device__ __forceinline__ void load16s(float d[16], const float* p) {
    const float4* p4 = (const float4*)p;
    float4 a = p4[0], b = p4[1], c = p4[2], e = p4[3];
    d[0]=a.x; d[1]=a.y; d[2]=a.z; d[3]=a.w;
    d[4]=b.x; d[5]=b.y; d[6]=b.z; d[7]=b.w;
    d[8]=c.x; d[9]=c.y; d[10]=c.z; d[11]=c.w;
    d[12]=e.x; d[13]=e.y; d[14]=e.z; d[15]=e.w;
}
__device__ __forceinline__ void load16g(float d[16], const float* p) {
    float4 a = __ldcg((const float4*)p);
    float4 b = __ldcg((const float4*)p + 1);
    float4 c = __ldcg((const float4*)p + 2);
    float4 e = __ldcg((const float4*)p + 3);
    d[0]=a.x; d[1]=a.y; d[2]=a.z; d[3]=a.w;
    d[4]=b.x; d[5]=b.y; d[6]=b.z; d[7]=b.w;
    d[8]=c.x; d[9]=c.y; d[10]=c.z; d[11]=c.w;
    d[12]=e.x; d[13]=e.y; d[14]=e.z; d[15]=e.w;
}
__device__ __forceinline__ float tree16(const float v[16]) {
    float a0=v[0]+v[1], a1=v[2]+v[3], a2=v[4]+v[5], a3=v[6]+v[7];
    float a4=v[8]+v[9], a5=v[10]+v[11], a6=v[12]+v[13], a7=v[14]+v[15];
    float b0=a0+a1, b1=a2+a3, b2=a4+a5, b3=a6+a7;
    return (b0+b1)+(b2+b3);
}

// ---------------------------------------------------------------------------
// K0: convert W -> transposed bf16 pairs (86016 elements)
// ---------------------------------------------------------------------------
__global__ __launch_bounds__(256) void convert_w_kernel(
    const float* __restrict__ Wa,
    const float* __restrict__ Wsp,
    const float* __restrict__ Wst) {
    int idx = blockIdx.x * 256 + threadIdx.x;
    if (idx >= kColsTot * kK2) return;
    int k2 = idx / kColsTot;
    int col = idx - k2 * kColsTot;
    const float* base; int stride, off;
    if (col < 288)      { base = Wa;  stride = 288; off = col; }
    else if (col < 320) { base = Wsp; stride = 32;  off = col - 288; }
    else                { base = Wst; stride = 16;  off = col - 320; }
    float x0 = base[(2 * k2    ) * stride + off];
    float x1 = base[(2 * k2 + 1) * stride + off];
    g_WbT[col * kK2 + k2] = pack_bf16(x0, x1);
}

// ---------------------------------------------------------------------------
// K1: fused — A-pack, GEMM, softmax, compose(+y), serial scan, y-dot tot
// ---------------------------------------------------------------------------
__global__ __launch_bounds__(kThreads) void fused_kernel(
    const float* __restrict__ s_i,
    const void* __restrict__ actions_raw,
    float* __restrict__ out) {
    extern __shared__ __align__(16) u32 smem[];
    u32* smA = smem + kOffA;
    u32* smW = smem + kOffW;
    float* smL = (float*)(smem + kOffW);     // logits alias W buf0 after GEMM
    float* sE0 = (float*)(smem + kOffE0);
    float* sE1 = (float*)(smem + kOffE1);
    float* sEs = (float*)(smem + kOffEs);
    float* sEa = (float*)(smem + kOffEa);
    float* sY  = (float*)(smem + kOffY);
    __shared__ int s_is64;

    const int tid  = threadIdx.x;
    const int blk  = blockIdx.x;
    const int row0 = blk * kRowsPerBlk;

    if (tid == 0) {
        const unsigned* w = (const unsigned*)actions_raw;
        unsigned acc = 0;
#pragma unroll
        for (int j = 1; j < 64; j += 2) acc |= w[j];
        s_is64 = (acc == 0u) ? 1 : 0;
    }

    // ---- Phase 1a: W prestage (tiles p0, p0+1) + in-register A-pack ----
    const int p0 = blk & (kNIt - 1);
    {
        int tk2 = p0 * kTileK2;
#pragma unroll
        for (int h = 0; h < 4; h++) {
            int q = tid + h * kThreads;
            int col = q >> 3, ch = q & 7;
            cp_async16(smW + col * kWStrideU + ch * 4,
                       g_WbT + col * kK2 + tk2 + ch * 4);
        }
        CP_COMMIT();
        int tk2b = (((p0 + 1) & (kNIt - 1)) * kTileK2);
#pragma unroll
        for (int h = 0; h < 4; h++) {
            int q = tid + h * kThreads;
            int col = q >> 3, ch = q & 7;
            cp_async16(smW + kWTileU + col * kWStrideU + ch * 4,
                       g_WbT + col * kK2 + tk2b + ch * 4);
        }
        CP_COMMIT();
    }
#pragma unroll
    for (int h = 0; h < 2; h++) {
        int q = tid + h * kThreads;
        if (q < 1024) {
            int r  = q >> 6;
            int ch = q & 63;
            int gr = row0 + r;
            float4 f0 = make_float4(0.f, 0.f, 0.f, 0.f);
            float4 f1 = f0;
            if (gr <= kT) {
                const float4* src = (const float4*)(s_i + gr * kS + ch * 8);
                f0 = src[0];
                f1 = src[1];
            }
            uint4 pk;
            pk.x = pack_bf16(f0.x, f0.y);
            pk.y = pack_bf16(f0.z, f0.w);
            pk.z = pack_bf16(f1.x, f1.y);
            pk.w = pack_bf16(f1.z, f1.w);
            *(uint4*)(smA + r * kAStrideU + ch * 4) = pk;
        }
    }

    // ---- Phase 1b: bf16 tensor-core GEMM (m16n8k16) ----
    const int lane = tid & 31;
    const int wid  = tid >> 5;
    const int g    = lane >> 2;
    const int t    = lane & 3;
    const int cb0  = wid * 16;
    const int cb1  = cb0 + 8;

    float c0[4] = {0.f, 0.f, 0.f, 0.f};
    float c1[4] = {0.f, 0.f, 0.f, 0.f};

    for (int i = 0; i < kNIt; i++) {
        if (i == kNIt - 1) { CP_WAIT0(); } else { CP_WAIT1(); }
        __syncthreads();
        if (i + 2 < kNIt) {
            u32* d = smW + ((i + 2) % 3) * kWTileU;
            int tk2 = (((p0 + i + 2) & (kNIt - 1)) * kTileK2);
#pragma unroll
            for (int h = 0; h < 4; h++) {
                int q = tid + h * kThreads;
                int col = q >> 3, ch = q & 7;
                cp_async16(d + col * kWStrideU + ch * 4,
                           g_WbT + col * kK2 + tk2 + ch * 4);
            }
            CP_COMMIT();
        }
        const int phys = (p0 + i) & (kNIt - 1);
        const u32* wt = smW + (i % 3) * kWTileU;
        const int kb2 = phys * kTileK2;
#pragma unroll
        for (int kk = 0; kk < 4; kk++) {
            const int o  = kb2 + kk * 8;
            const int ot = kk * 8;
            u32 a0 = smA[(g    ) * kAStrideU + o + t    ];
            u32 a1 = smA[(g + 8) * kAStrideU + o + t    ];
            u32 a2 = smA[(g    ) * kAStrideU + o + t + 4];
            u32 a3 = smA[(g + 8) * kAStrideU + o + t + 4];
            u32 b00 = wt[(cb0 + g) * kWStrideU + ot + t    ];
            u32 b01 = wt[(cb0 + g) * kWStrideU + ot + t + 4];
            u32 b10 = wt[(cb1 + g) * kWStrideU + ot + t    ];
            u32 b11 = wt[(cb1 + g) * kWStrideU + ot + t + 4];
            mma_bf16(c0, a0, a1, a2, a3, b00, b01);
            mma_bf16(c1, a0, a1, a2, a3, b10, b11);
        }
    }
    __syncthreads();

    // ---- Phase 1c: epilogue — scatter C fragments to smL[r*336 + c] ----
    {
        int col0 = cb0 + 2 * t;
        smL[(g    ) * kColsTot + col0    ] = c0[0];
        smL[(g    ) * kColsTot + col0 + 1] = c0[1];
        smL[(g + 8) * kColsTot + col0    ] = c0[2];
        smL[(g + 8) * kColsTot + col0 + 1] = c0[3];
        int col1 = cb1 + 2 * t;
        smL[(g    ) * kColsTot + col1    ] = c1[0];
        smL[(g    ) * kColsTot + col1 + 1] = c1[1];
        smL[(g + 8) * kColsTot + col1    ] = c1[2];
        smL[(g + 8) * kColsTot + col1 + 1] = c1[3];
    }
    __syncthreads();

    // ---- Phase 1d: softmaxes ----
    if (tid < 256) {
        const int r = tid >> 4;
        const int b = tid & 15;
        const int i = row0 + r;
        const bool valid = (i <= kT);
        const int is64 = s_is64;

        if (valid) {
            if (i < kT) {
                int a;
                if (is64) a = (int)((const long long*)actions_raw)[i];
                else      a = ((const int*)actions_raw)[i];
                const float* L = &smL[r * kColsTot + b * kA];
                float m = L[0];
#pragma unroll
                for (int j = 1; j < kA; j++) m = fmaxf(m, L[j]);
                float s = 0.0f;
#pragma unroll
                for (int j = 0; j < kA; j++) s += __expf(L[j] - m);
                sEa[r * kB + b] = __expf(L[a] - m) / s;
            }
            float x0 = smL[r * kColsTot + 288 + 2 * b];
            float x1 = smL[r * kColsTot + 288 + 2 * b + 1];
            float m = fmaxf(x0, x1);
            float e0 = __expf(x0 - m), e1 = __expf(x1 - m);
            float inv = 1.0f / (e0 + e1);
            float es0 = e0 * inv;
            sE0[r * kB + b] = es0;
            sE1[r * kB + b] = e1 * inv;
            if (i == kT) { g_es0_fin[b] = es0; __threadfence(); }
        }
        {
            float x = smL[r * kColsTot + 320 + b];
            float m = x;
            m = fmaxf(m, __shfl_xor_sync(0xFFFFFFFFu, m, 1));
            m = fmaxf(m, __shfl_xor_sync(0xFFFFFFFFu, m, 2));
            m = fmaxf(m, __shfl_xor_sync(0xFFFFFFFFu, m, 4));
            m = fmaxf(m, __shfl_xor_sync(0xFFFFFFFFu, m, 8));
            float e = __expf(x - m);
            float s = e;
            s += __shfl_xor_sync(0xFFFFFFFFu, s, 1);
            s += __shfl_xor_sync(0xFFFFFFFFu, s, 2);
            s += __shfl_xor_sync(0xFFFFFFFFu, s, 4);
            s += __shfl_xor_sync(0xFFFFFFFFu, s, 8);
            if (valid) sEs[r * kB + b] = e / s;
        }
    }
    __syncthreads();

    // ---- Phase 2: compose (+ y into smem); signal g_mcnt ----
    if (blk < kNBlks && tid < 32) {
        const int k = tid & 15;
        float P16[16];
#pragma unroll
        for (int j = 0; j < 16; j++) P16[j] = (j == k) ? 1.0f : 0.0f;
        for (int s = 0; s < kBlkSteps; s++) {
            if (!(blk == 0 && s == 0)) {
                float s0[16], s1[16], vv[16];
                load16s(s0, &sE0[s * kB]);
                load16s(s1, &sE1[s * kB]);
                load16s(vv, &sEs[s * kB]);
                float m[16];
#pragma unroll
                for (int j = 0; j < 16; j++) m[j] = s1[j] * P16[j];
                float w = tree16(m);
#pragma unroll
                for (int j = 0; j < 16; j++)
                    P16[j] = fmaf(s0[j], P16[j], (vv[j] * EXP_NEG_PEN) * w);
            }
            // y_s[k] = sum_j eac_s[j] * P[j,k]
            float ea[16];
            load16s(ea, &sEa[s * kB]);
            float m2[16];
#pragma unroll
            for (int j = 0; j < 16; j++) m2[j] = ea[j] * P16[j];
            float y = tree16(m2);
            if (tid < 16) sY[s * kB + k] = y;
        }
        if (tid < 16) {
#pragma unroll
            for (int j = 0; j < 16; j++)
                g_M[blk * 256 + j * 16 + k] = P16[j];
        }
        __threadfence();
        __syncwarp();
        if (tid == 0) atomicAdd(&g_mcnt, 1u);
    }

    // ---- Phase 3: serial scan (block 0 only waits for M) ----
    if (blk == 0) {
        if (tid == 0) {
            volatile unsigned* vm = &g_mcnt;
            while (*vm < (unsigned)kNBlks) { __nanosleep(64); }
            g_mcnt = 0;
            __threadfence();
        }
        __syncthreads();

        float* smM = (float*)smem;   // 128 matrices, stride 320, ends 40960
#pragma unroll
        for (int h = 0; h < 13; h++) {
            int q = tid + h * kThreads;
            if (q < 8192) {
                int m   = q >> 6;
                int rem = q & 63;
                int row = rem >> 2;
                int ch  = rem & 3;
                cp_async16(smM + m * kMStrideMat + row * kMStrideRow + ch * 4,
                           (const float*)g_M + q * 4);
            }
        }
        CP_COMMIT();
        CP_WAIT0();
        __syncthreads();

        if (tid < 32) {
            const int r = tid & 15;
            float Q[16];
            load16s(Q, &sEs[0]);     // block 0 owns row 0 (start softmax)
            if (tid < 16) g_chk[tid] = Q[tid];
            if (tid == 0) g_Eb[0] = 0;
            int E = 0;

            const float* Mr = smM + r * kMStrideRow;
            float4 a0 = *(const float4*)(Mr + 0);
            float4 a1 = *(const float4*)(Mr + 4);
            float4 a2 = *(const float4*)(Mr + 8);
            float4 a3 = *(const float4*)(Mr + 12);

            for (int j = 0; j < kNBlks; j++) {
                float4 b0, b1, b2, b3;
                if (j + 1 < kNBlks) {
                    const float* Mn = smM + (j + 1) * kMStrideMat + r * kMStrideRow;
                    b0 = *(const float4*)(Mn + 0);
                    b1 = *(const float4*)(Mn + 4);
                    b2 = *(const float4*)(Mn + 8);
                    b3 = *(const float4*)(Mn + 12);
                }
                float mm[16] = {a0.x, a0.y, a0.z, a0.w, a1.x, a1.y, a1.z, a1.w,
                                a2.x, a2.y, a2.z, a2.w, a3.x, a3.y, a3.z, a3.w};
                float pr[16];
#pragma unroll
                for (int kk = 0; kk < 16; kk++) pr[kk] = mm[kk] * Q[kk];
                float outr = tree16(pr);

                float Qn[16];
#pragma unroll
                for (int kk = 0; kk < 16; kk++)
                    Qn[kk] = __shfl_sync(0xFFFFFFFFu, outr, kk);

                if ((j & 3) == 3) {
                    float ss = tree16(Qn);
                    int e = ((__float_as_int(ss) >> 23) & 0xFF) - 127;
                    float sc = __int_as_float((127 - e) << 23);
#pragma unroll
                    for (int kk = 0; kk < 16; kk++) Q[kk] = Qn[kk] * sc;
                    E += e;
                } else {
#pragma unroll
                    for (int kk = 0; kk < 16; kk++) Q[kk] = Qn[kk];
                }

                if (tid < 16) g_chk[(j + 1) * kB + tid] = Q[tid];
                if (tid == 0) g_Eb[j + 1] = E;
                a0 = b0; a1 = b1; a2 = b2; a3 = b3;
            }
            __threadfence();
        }
    }

    gbar(0, kGrid);   // checkpoints ready

    // ---- Phase 4: y-dot tot (16 threads/block) + atomic reduction ----
    if (blk < kNBlks && tid < 16) {
        float c[16];
        load16g(c, &g_chk[blk * kB]);
        const int E = __ldcg(&g_Eb[blk]);
        float y[16];
        load16s(y, &sY[tid * kB]);      // this thread's step
        float pr[16];
#pragma unroll
        for (int kk = 0; kk < 16; kk++) pr[kk] = y[kk] * c[kk];
        float u = tree16(pr);
        double acc = (double)__logf(u);

#pragma unroll
        for (int o = 8; o > 0; o >>= 1)
            acc += __shfl_down_sync(0x0000FFFFu, acc, o, 16);

        if (tid == 0) {
            acc += (double)(kBlkSteps * E) * LN2;
            if (blk == kNBlks - 1) {
                float f[16], cf[16];
                load16g(f, g_es0_fin);
                load16g(cf, &g_chk[kNBlks * kB]);
                float p2[16];
#pragma unroll
                for (int kk = 0; kk < 16; kk++) p2[kk] = f[kk] * cf[kk];
                float uf = tree16(p2);
                acc += (double)__logf(uf) + (double)__ldcg(&g_Eb[kNBlks]) * LN2;
            }
            atomicAdd(&g_tot, acc);
            __threadfence();
            unsigned old = atomicAdd(&g_rcnt, 1u);
            if (old == (unsigned)(kNBlks - 1)) {
                __threadfence();
                double v = atomicAdd(&g_tot, 0.0);
                out[0] = (float)v;
                g_rcnt = 0u;
                g_tot = 0.0;
                __threadfence();
            }
        }
    }
}

// ---------------------------------------------------------------------------
// Launch
// ---------------------------------------------------------------------------
extern "C" void kernel_launch(void* const* d_in, const int* in_sizes, int n_in,
                              void* d_out, int out_size) {
    const float* s_i = (const float*)d_in[0];
    const float* Wa  = (const float*)d_in[1];
    const float* Wsp = (const float*)d_in[2];
    const float* Wst = (const float*)d_in[3];
    const void*  act = d_in[4];

    cudaFuncSetAttribute(fused_kernel,
                         cudaFuncAttributeMaxDynamicSharedMemorySize,
                         kSmemBytes);

    convert_w_kernel<<<(kColsTot * kK2 + 255) / 256, 256>>>(Wa, Wsp, Wst);
    fused_kernel<<<kGrid, kThreads, kSmemBytes>>>(s_i, act, (float*)d_out);
}